// round 9
// baseline (speedup 1.0000x reference)
#include <cuda_runtime.h>
#include <cstdint>

#define TWO_PI_F 6.28318530717958647692f

namespace {

constexpr int B = 4, S = 4096, V = 64, D = 128;

struct __align__(16) PosSmem {
    float xs2[2][V][2];    // [pair][j][half]  pair p = batches (2p, 2p+1)
    float hs2[2][V][2];
    float ls2[2][D][2];
    float h1s2[2][D][2];
    float red[2][B][2];    // [sum/sumsq][batch][warp-in-position]
};

// ---- f32x2 packed helpers --------------------------------------------------
__device__ __forceinline__ unsigned long long dup2(float a) {
    unsigned long long r; unsigned int u = __float_as_uint(a);
    asm("mov.b64 %0, {%1, %1};" : "=l"(r) : "r"(u));
    return r;
}
__device__ __forceinline__ unsigned long long pk2(float a, float b) {
    unsigned long long r;
    asm("mov.b64 %0, {%1, %2};" : "=l"(r) : "r"(__float_as_uint(a)), "r"(__float_as_uint(b)));
    return r;
}
__device__ __forceinline__ float2 unpk(unsigned long long v) {
    unsigned int lo, hi;
    asm("mov.b64 {%0, %1}, %2;" : "=r"(lo), "=r"(hi) : "l"(v));
    return make_float2(__uint_as_float(lo), __uint_as_float(hi));
}
__device__ __forceinline__ void ffma2(unsigned long long& d, unsigned long long a,
                                      unsigned long long b) {
    asm("fma.rn.f32x2 %0, %1, %2, %0;" : "+l"(d) : "l"(a), "l"(b));
}
__device__ __forceinline__ unsigned long long addp(unsigned long long a,
                                                   unsigned long long b) {
    unsigned long long r;
    asm("add.rn.f32x2 %0, %1, %2;" : "=l"(r) : "l"(a), "l"(b));
    return r;
}

// slow path: exact integer range reduction (q off-by-one shifts by a full
// period, invisible to cos).
__device__ __forceinline__ float phase_slow(float sf, float pf, float rcp) {
    float q = floorf(sf * rcp);
    float r = fmaf(-q, pf, sf);
    return __cosf(TWO_PI_F * (r * rcp));
}
// fast path: valid when p > s (floor(s/p)=0) -> arg = (2*pi*s)*rcp directly.
__device__ __forceinline__ float phase_fast(float sf2, float rcp) {
    return __cosf(sf2 * rcp);
}

} // namespace

// ---- packed weight scratch (position-invariant, rebuilt each launch) -------
// pairwise-j float4 layout [j2][i]: (w_j, rcp_j, w_{j+1}, rcp_{j+1})
__device__ float4 g_pk0q[(V / 2) * V];   // charP
__device__ float4 g_pk1q[(D / 2) * D];   // P1
__device__ float4 g_pk2q[(D / 2) * D];   // P2
__device__ float4 g_mrq [(V / 2) * D];   // (M1_j, R1_j, M1_{j+1}, R1_{j+1})
__device__ float4 g_M2q [(D / 4) * D];   // 4 consecutive j of M2 row i

extern "C" __global__ void __launch_bounds__(256)
prep_weights(const float* __restrict__ charP, const float* __restrict__ M1,
             const float* __restrict__ R1,    const float* __restrict__ P1,
             const float* __restrict__ P2,    const float* __restrict__ M2)
{
    int t = blockIdx.x * blockDim.x + threadIdx.x;
    if (t < 2048) {                                   // charP pairs
        int j2 = t >> 6, i = t & 63;
        int j0 = 2 * j2;
        g_pk0q[t] = make_float4(charP[i * V + j0],     1.0f / (float)(i * V + j0 + 2),
                                charP[i * V + j0 + 1], 1.0f / (float)(i * V + j0 + 3));
    } else if (t < 10240) {                           // P1 pairs
        int u = t - 2048; int j2 = u >> 7, i = u & 127;
        int j0 = 2 * j2;
        g_pk1q[u] = make_float4(P1[i * D + j0],     1.0f / (float)(i * D + j0 + 2),
                                P1[i * D + j0 + 1], 1.0f / (float)(i * D + j0 + 3));
    } else if (t < 18432) {                           // P2 pairs
        int u = t - 10240; int j2 = u >> 7, i = u & 127;
        int j0 = 2 * j2;
        g_pk2q[u] = make_float4(P2[i * D + j0],     1.0f / (float)(i * D + j0 + 2),
                                P2[i * D + j0 + 1], 1.0f / (float)(i * D + j0 + 3));
    } else if (t < 22528) {                           // M1/R1 pairs
        int u = t - 18432; int j2 = u >> 7, i = u & 127;
        int j0 = 2 * j2;
        g_mrq[u] = make_float4(M1[i * V + j0],     R1[i * V + j0],
                               M1[i * V + j0 + 1], R1[i * V + j0 + 1]);
    } else if (t < 26624) {                           // M2 quads
        int u = t - 22528; int j4 = u >> 7, i = u & 127;
        g_M2q[u] = *reinterpret_cast<const float4*>(&M2[i * D + 4 * j4]);
    }
}

namespace {

// pos_nk accumulation over D for two rows (A maybe-slow, B always fast).
template <bool FA>
__device__ __forceinline__ void posnk_accum(
    const float4* __restrict__ tbl, const float* __restrict__ xbase,
    float sf, float sf2, float pb0, int i0, int i1,
    unsigned long long (&acc)[2][2])
{
    #pragma unroll 4
    for (int j2 = 0; j2 < D / 2; ++j2) {
        ulonglong2 x0 = *reinterpret_cast<const ulonglong2*>(xbase + (2 * j2) * 2);
        ulonglong2 x1 = *reinterpret_cast<const ulonglong2*>(xbase + (D + 2 * j2) * 2);
        float4 wA = tbl[j2 * D + i0];
        float4 wB = tbl[j2 * D + i1];
        float j0f = (float)(2 * j2);
        float phA0 = FA ? phase_fast(sf2, wA.y) : phase_slow(sf, pb0 + j0f, wA.y);
        float phA1 = FA ? phase_fast(sf2, wA.w) : phase_slow(sf, pb0 + j0f + 1.f, wA.w);
        float phB0 = phase_fast(sf2, wB.y);
        float phB1 = phase_fast(sf2, wB.w);
        unsigned long long aA0 = dup2(wA.x * phA0), aA1 = dup2(wA.z * phA1);
        unsigned long long aB0 = dup2(wB.x * phB0), aB1 = dup2(wB.z * phB1);
        ffma2(acc[0][0], aA0, x0.x); ffma2(acc[0][1], aA0, x1.x);
        ffma2(acc[0][0], aA1, x0.y); ffma2(acc[0][1], aA1, x1.y);
        ffma2(acc[1][0], aB0, x0.x); ffma2(acc[1][1], aB0, x1.x);
        ffma2(acc[1][0], aB1, x0.y); ffma2(acc[1][1], aB1, x1.y);
    }
}

} // namespace

extern "C" __global__ void __launch_bounds__(128)
hier_kernel(const int* __restrict__ tokens, const int* __restrict__ positions,
            const float* __restrict__ emb,
            const float* __restrict__ g1, const float* __restrict__ b1v,
            const float* __restrict__ g2, const float* __restrict__ b2v,
            float* __restrict__ out)
{
    __shared__ PosSmem sm[2];

    const int tid  = (int)threadIdx.x;
    const int ph   = tid >> 6;            // position within CTA (0/1)
    const int t    = tid & 63;            // thread within position
    const int lane = tid & 31;
    const int wp   = (tid >> 5) & 1;      // warp within position
    const int sidx = blockIdx.x * 2 + ph;
    const float sf  = (float)positions[sidx];
    const float sf2 = TWO_PI_F * sf;
    PosSmem& PS = sm[ph];

    // ---- gather char embeddings ------------------------------------------
    {
        #pragma unroll
        for (int b = 0; b < B; ++b) {
            int tk = tokens[b * S + sidx];
            PS.xs2[b >> 1][t][b & 1] = emb[tk * V + t];
        }
    }
    __syncthreads();

    // ---- layer 0: h = (char_P .* phi64) @ x ------------------------------
    {
        const int i = t;
        const float pbase = (float)(i * V + 2);
        unsigned long long acc0 = 0, acc1 = 0;
        #pragma unroll 8
        for (int j2 = 0; j2 < V / 2; ++j2) {
            ulonglong2 x0 = *reinterpret_cast<const ulonglong2*>(&PS.xs2[0][2 * j2][0]);
            ulonglong2 x1 = *reinterpret_cast<const ulonglong2*>(&PS.xs2[1][2 * j2][0]);
            float4 w = g_pk0q[j2 * V + i];
            float j0f = (float)(2 * j2);
            float a0 = w.x * phase_slow(sf, pbase + j0f, w.y);
            float a1 = w.z * phase_slow(sf, pbase + j0f + 1.f, w.w);
            unsigned long long ad0 = dup2(a0), ad1 = dup2(a1);
            ffma2(acc0, ad0, x0.x); ffma2(acc1, ad0, x1.x);
            ffma2(acc0, ad1, x0.y); ffma2(acc1, ad1, x1.y);
        }
        *reinterpret_cast<unsigned long long*>(&PS.hs2[0][i][0]) = acc0;
        *reinterpret_cast<unsigned long long*>(&PS.hs2[1][i][0]) = acc1;
    }
    __syncthreads();

    const int i0 = t, i1 = t + 64;        // the two rows this thread owns

    auto layernorm2 = [&](float (&tv)[2][B], const float* gg, const float* bb,
                          float (&nv)[2][B]) {
        float s1[B], s2[B];
        #pragma unroll
        for (int b = 0; b < B; ++b) {
            s1[b] = tv[0][b] + tv[1][b];
            s2[b] = tv[0][b] * tv[0][b] + tv[1][b] * tv[1][b];
        }
        #pragma unroll
        for (int o = 16; o; o >>= 1) {
            #pragma unroll
            for (int b = 0; b < B; ++b) {
                s1[b] += __shfl_xor_sync(0xffffffffu, s1[b], o);
                s2[b] += __shfl_xor_sync(0xffffffffu, s2[b], o);
            }
        }
        if (lane == 0) {
            #pragma unroll
            for (int b = 0; b < B; ++b) {
                PS.red[0][b][wp] = s1[b];
                PS.red[1][b][wp] = s2[b];
            }
        }
        __syncthreads();
        const float gA = gg[i0], bA = bb[i0];
        const float gB = gg[i1], bB = bb[i1];
        #pragma unroll
        for (int b = 0; b < B; ++b) {
            float su = PS.red[0][b][0] + PS.red[0][b][1];
            float sq = PS.red[1][b][0] + PS.red[1][b][1];
            float mu  = su * (1.0f / D);
            float var = fmaf(sq, 1.0f / D, -mu * mu);
            float rs  = rsqrtf(var + 1e-5f);
            nv[0][b] = fmaf((tv[0][b] - mu) * rs, gA, bA);
            nv[1][b] = fmaf((tv[1][b] - mu) * rs, gB, bB);
        }
    };

    // ---- layer 1: t1 = M1 @ h and rv = R1 @ h (fused, 2 rows) ------------
    unsigned long long t1p[2][2] = {{0ull,0ull},{0ull,0ull}};
    unsigned long long rvp[2][2] = {{0ull,0ull},{0ull,0ull}};
    {
        #pragma unroll 8
        for (int j2 = 0; j2 < V / 2; ++j2) {
            ulonglong2 x0 = *reinterpret_cast<const ulonglong2*>(&PS.hs2[0][2 * j2][0]);
            ulonglong2 x1 = *reinterpret_cast<const ulonglong2*>(&PS.hs2[1][2 * j2][0]);
            float4 wA = g_mrq[j2 * D + i0];
            float4 wB = g_mrq[j2 * D + i1];
            unsigned long long mA0 = dup2(wA.x), rA0 = dup2(wA.y);
            unsigned long long mA1 = dup2(wA.z), rA1 = dup2(wA.w);
            unsigned long long mB0 = dup2(wB.x), rB0 = dup2(wB.y);
            unsigned long long mB1 = dup2(wB.z), rB1 = dup2(wB.w);
            ffma2(t1p[0][0], mA0, x0.x); ffma2(t1p[0][1], mA0, x1.x);
            ffma2(t1p[0][0], mA1, x0.y); ffma2(t1p[0][1], mA1, x1.y);
            ffma2(t1p[1][0], mB0, x0.x); ffma2(t1p[1][1], mB0, x1.x);
            ffma2(t1p[1][0], mB1, x0.y); ffma2(t1p[1][1], mB1, x1.y);
            ffma2(rvp[0][0], rA0, x0.x); ffma2(rvp[0][1], rA0, x1.x);
            ffma2(rvp[0][0], rA1, x0.y); ffma2(rvp[0][1], rA1, x1.y);
            ffma2(rvp[1][0], rB0, x0.x); ffma2(rvp[1][1], rB0, x1.x);
            ffma2(rvp[1][0], rB1, x0.y); ffma2(rvp[1][1], rB1, x1.y);
        }
    }
    // layernorm(t1) -> ls2
    {
        float tv[2][B], nv[2][B];
        #pragma unroll
        for (int r = 0; r < 2; ++r) {
            float2 a0 = unpk(t1p[r][0]), a1 = unpk(t1p[r][1]);
            tv[r][0] = a0.x; tv[r][1] = a0.y; tv[r][2] = a1.x; tv[r][3] = a1.y;
        }
        layernorm2(tv, g1, b1v, nv);
        *reinterpret_cast<unsigned long long*>(&PS.ls2[0][i0][0]) = pk2(nv[0][0], nv[0][1]);
        *reinterpret_cast<unsigned long long*>(&PS.ls2[1][i0][0]) = pk2(nv[0][2], nv[0][3]);
        *reinterpret_cast<unsigned long long*>(&PS.ls2[0][i1][0]) = pk2(nv[1][0], nv[1][1]);
        *reinterpret_cast<unsigned long long*>(&PS.ls2[1][i1][0]) = pk2(nv[1][2], nv[1][3]);
    }
    __syncthreads();

    const float pb0 = (float)(i0 * D + 2);

    // ---- layer 1 pos_nk + residual ---------------------------------------
    unsigned long long h1p[2][2] = {{0ull,0ull},{0ull,0ull}};
    {
        const float* xbase = &PS.ls2[0][0][0];
        if (i0 >= 32) posnk_accum<true >(g_pk1q, xbase, sf, sf2, pb0, i0, i1, h1p);
        else          posnk_accum<false>(g_pk1q, xbase, sf, sf2, pb0, i0, i1, h1p);
        #pragma unroll
        for (int r = 0; r < 2; ++r) {
            h1p[r][0] = addp(h1p[r][0], rvp[r][0]);
            h1p[r][1] = addp(h1p[r][1], rvp[r][1]);
        }
        *reinterpret_cast<unsigned long long*>(&PS.h1s2[0][i0][0]) = h1p[0][0];
        *reinterpret_cast<unsigned long long*>(&PS.h1s2[1][i0][0]) = h1p[0][1];
        *reinterpret_cast<unsigned long long*>(&PS.h1s2[0][i1][0]) = h1p[1][0];
        *reinterpret_cast<unsigned long long*>(&PS.h1s2[1][i1][0]) = h1p[1][1];
    }
    __syncthreads();

    // ---- layer 2: t2 = M2 @ h1 (4-j packed weights) -----------------------
    unsigned long long t2p[2][2] = {{0ull,0ull},{0ull,0ull}};
    {
        #pragma unroll 4
        for (int j4 = 0; j4 < D / 4; ++j4) {
            ulonglong2 xa0 = *reinterpret_cast<const ulonglong2*>(&PS.h1s2[0][4 * j4][0]);
            ulonglong2 xb0 = *reinterpret_cast<const ulonglong2*>(&PS.h1s2[0][4 * j4 + 2][0]);
            ulonglong2 xa1 = *reinterpret_cast<const ulonglong2*>(&PS.h1s2[1][4 * j4][0]);
            ulonglong2 xb1 = *reinterpret_cast<const ulonglong2*>(&PS.h1s2[1][4 * j4 + 2][0]);
            float4 mA = g_M2q[j4 * D + i0];
            float4 mB = g_M2q[j4 * D + i1];
            unsigned long long a0 = dup2(mA.x), a1 = dup2(mA.y), a2 = dup2(mA.z), a3 = dup2(mA.w);
            unsigned long long c0 = dup2(mB.x), c1 = dup2(mB.y), c2 = dup2(mB.z), c3 = dup2(mB.w);
            ffma2(t2p[0][0], a0, xa0.x); ffma2(t2p[0][1], a0, xa1.x);
            ffma2(t2p[0][0], a1, xa0.y); ffma2(t2p[0][1], a1, xa1.y);
            ffma2(t2p[0][0], a2, xb0.x); ffma2(t2p[0][1], a2, xb1.x);
            ffma2(t2p[0][0], a3, xb0.y); ffma2(t2p[0][1], a3, xb1.y);
            ffma2(t2p[1][0], c0, xa0.x); ffma2(t2p[1][1], c0, xa1.x);
            ffma2(t2p[1][0], c1, xa0.y); ffma2(t2p[1][1], c1, xa1.y);
            ffma2(t2p[1][0], c2, xb0.x); ffma2(t2p[1][1], c2, xb1.x);
            ffma2(t2p[1][0], c3, xb0.y); ffma2(t2p[1][1], c3, xb1.y);
        }
    }
    // layernorm(t2) -> ls2 (reuse)
    {
        float tv[2][B], nv[2][B];
        #pragma unroll
        for (int r = 0; r < 2; ++r) {
            float2 a0 = unpk(t2p[r][0]), a1 = unpk(t2p[r][1]);
            tv[r][0] = a0.x; tv[r][1] = a0.y; tv[r][2] = a1.x; tv[r][3] = a1.y;
        }
        layernorm2(tv, g2, b2v, nv);
        __syncthreads();
        *reinterpret_cast<unsigned long long*>(&PS.ls2[0][i0][0]) = pk2(nv[0][0], nv[0][1]);
        *reinterpret_cast<unsigned long long*>(&PS.ls2[1][i0][0]) = pk2(nv[0][2], nv[0][3]);
        *reinterpret_cast<unsigned long long*>(&PS.ls2[0][i1][0]) = pk2(nv[1][0], nv[1][1]);
        *reinterpret_cast<unsigned long long*>(&PS.ls2[1][i1][0]) = pk2(nv[1][2], nv[1][3]);
    }
    __syncthreads();

    // ---- layer 2 pos_nk + shared residual t2 ------------------------------
    unsigned long long ovp[2][2] = {{0ull,0ull},{0ull,0ull}};
    {
        const float* xbase = &PS.ls2[0][0][0];
        if (i0 >= 32) posnk_accum<true >(g_pk2q, xbase, sf, sf2, pb0, i0, i1, ovp);
        else          posnk_accum<false>(g_pk2q, xbase, sf, sf2, pb0, i0, i1, ovp);
    }
    {
        float2 o00 = unpk(addp(ovp[0][0], t2p[0][0]));   // row i0, batches 0/1
        float2 o01 = unpk(addp(ovp[0][1], t2p[0][1]));   // row i0, batches 2/3
        float2 o10 = unpk(addp(ovp[1][0], t2p[1][0]));   // row i1, batches 0/1
        float2 o11 = unpk(addp(ovp[1][1], t2p[1][1]));   // row i1, batches 2/3
        out[(0 * S + sidx) * D + i0] = o00.x;
        out[(1 * S + sidx) * D + i0] = o00.y;
        out[(2 * S + sidx) * D + i0] = o01.x;
        out[(3 * S + sidx) * D + i0] = o01.y;
        out[(0 * S + sidx) * D + i1] = o10.x;
        out[(1 * S + sidx) * D + i1] = o10.y;
        out[(2 * S + sidx) * D + i1] = o11.x;
        out[(3 * S + sidx) * D + i1] = o11.y;
    }
}

extern "C" void kernel_launch(void* const* d_in, const int* in_sizes, int n_in,
                              void* d_out, int out_size) {
    const int*   tokens    = (const int*)d_in[0];
    const int*   positions = (const int*)d_in[1];
    const float* emb       = (const float*)d_in[2];
    const float* charP     = (const float*)d_in[3];
    const float* M1        = (const float*)d_in[4];
    const float* P1        = (const float*)d_in[5];
    const float* g1        = (const float*)d_in[6];
    const float* b1        = (const float*)d_in[7];
    const float* R1        = (const float*)d_in[8];
    const float* M2        = (const float*)d_in[9];
    const float* P2        = (const float*)d_in[10];
    const float* g2        = (const float*)d_in[11];
    const float* b2        = (const float*)d_in[12];
    float* out = (float*)d_out;

    prep_weights<<<(26624 + 255) / 256, 256>>>(charP, M1, R1, P1, P2, M2);

    hier_kernel<<<S / 2, 128>>>(tokens, positions, emb, g1, b1, g2, b2, out);
}

// round 10
// speedup vs baseline: 1.0027x; 1.0027x over previous
#include <cuda_runtime.h>
#include <cstdint>

#define TWO_PI_F 6.28318530717958647692f

namespace {

constexpr int B = 4, S = 4096, V = 64, D = 128;

struct __align__(16) PosSmem {
    float xs2[2][V][2];    // [pair][j][half]  pair p = batches (2p, 2p+1)
    float hs2[2][V][2];
    float ls2[2][D][2];
    float h1s2[2][D][2];
    float red[2][B][2];    // [sum/sumsq][batch][warp-in-position]
};

// ---- f32x2 packed helpers --------------------------------------------------
__device__ __forceinline__ unsigned long long dup2(float a) {
    unsigned long long r; unsigned int u = __float_as_uint(a);
    asm("mov.b64 %0, {%1, %1};" : "=l"(r) : "r"(u));
    return r;
}
__device__ __forceinline__ unsigned long long pk2(float a, float b) {
    unsigned long long r;
    asm("mov.b64 %0, {%1, %2};" : "=l"(r) : "r"(__float_as_uint(a)), "r"(__float_as_uint(b)));
    return r;
}
__device__ __forceinline__ float2 unpk(unsigned long long v) {
    unsigned int lo, hi;
    asm("mov.b64 {%0, %1}, %2;" : "=r"(lo), "=r"(hi) : "l"(v));
    return make_float2(__uint_as_float(lo), __uint_as_float(hi));
}
__device__ __forceinline__ void ffma2(unsigned long long& d, unsigned long long a,
                                      unsigned long long b) {
    asm("fma.rn.f32x2 %0, %1, %2, %0;" : "+l"(d) : "l"(a), "l"(b));
}
__device__ __forceinline__ unsigned long long addp(unsigned long long a,
                                                   unsigned long long b) {
    unsigned long long r;
    asm("add.rn.f32x2 %0, %1, %2;" : "=l"(r) : "l"(a), "l"(b));
    return r;
}

// slow path: exact integer range reduction (q off-by-one shifts by a full
// period, invisible to cos).
__device__ __forceinline__ float phase_slow(float sf, float pf, float rcp) {
    float q = floorf(sf * rcp);
    float r = fmaf(-q, pf, sf);
    return __cosf(TWO_PI_F * (r * rcp));
}
// fast path: valid when p > s (floor(s/p)=0) -> arg = (2*pi*s)*rcp directly.
__device__ __forceinline__ float phase_fast(float sf2, float rcp) {
    return __cosf(sf2 * rcp);
}

} // namespace

// ---- packed weight scratch (position-invariant, rebuilt each launch) -------
__device__ float2 g_pk0[V * V];     // [j][i]: (charPT, 1/(i*V+j+2))
__device__ float2 g_pk1[D * D];     // [j][i]: (P1T, 1/(i*D+j+2))
__device__ float2 g_pk2[D * D];     // [j][i]: (P2T, 1/(i*D+j+2))
__device__ float2 g_mr [V * D];     // [j][i]: (M1T, R1T)
__device__ float  g_M2T[D * D];     // [j][i]

extern "C" __global__ void __launch_bounds__(256)
prep_weights(const float* __restrict__ charP, const float* __restrict__ M1,
             const float* __restrict__ R1,    const float* __restrict__ P1,
             const float* __restrict__ P2,    const float* __restrict__ M2)
{
    int t = blockIdx.x * blockDim.x + threadIdx.x;
    if (t < 4096) {                                   // charP 64x64
        int j = t >> 6, i = t & 63;
        g_pk0[t] = make_float2(charP[i * V + j], 1.0f / (float)(i * V + j + 2));
    } else if (t < 20480) {                           // P1 128x128
        int u = t - 4096; int j = u >> 7, i = u & 127;
        g_pk1[u] = make_float2(P1[i * D + j], 1.0f / (float)(i * D + j + 2));
    } else if (t < 36864) {                           // P2 128x128
        int u = t - 20480; int j = u >> 7, i = u & 127;
        g_pk2[u] = make_float2(P2[i * D + j], 1.0f / (float)(i * D + j + 2));
    } else if (t < 45056) {                           // M1,R1 64x128
        int u = t - 36864; int j = u >> 7, i = u & 127;
        g_mr[u] = make_float2(M1[i * V + j], R1[i * V + j]);
    } else if (t < 61440) {                           // M2 128x128
        int u = t - 45056; int j = u >> 7, i = u & 127;
        g_M2T[u] = M2[i * D + j];
    }
}

namespace {

// pos_nk accumulation over D for two rows. Row B (i1 = i0+64 >= 64) always has
// period > 4095 >= s, so it is always fast; row A is fast iff i0 >= 32
// (warp-uniform -> template dispatch).
template <bool FA>
__device__ __forceinline__ void posnk_accum(
    const float2* __restrict__ tbl, const float* __restrict__ xbase,
    float sf, float sf2, float pb0, int i0, int i1,
    unsigned long long (&acc)[2][2])
{
    #pragma unroll 4
    for (int j2 = 0; j2 < D / 2; ++j2) {
        ulonglong2 x0 = *reinterpret_cast<const ulonglong2*>(xbase + (2 * j2) * 2);
        ulonglong2 x1 = *reinterpret_cast<const ulonglong2*>(xbase + (D + 2 * j2) * 2);
        #pragma unroll
        for (int e = 0; e < 2; ++e) {
            int j = 2 * j2 + e;
            float2 wA = tbl[j * D + i0];
            float2 wB = tbl[j * D + i1];
            float phA = FA ? phase_fast(sf2, wA.y)
                           : phase_slow(sf, pb0 + (float)j, wA.y);
            float phB = phase_fast(sf2, wB.y);
            unsigned long long adA = dup2(wA.x * phA);
            unsigned long long adB = dup2(wB.x * phB);
            unsigned long long xm0 = e ? x0.y : x0.x;
            unsigned long long xm1 = e ? x1.y : x1.x;
            ffma2(acc[0][0], adA, xm0); ffma2(acc[0][1], adA, xm1);
            ffma2(acc[1][0], adB, xm0); ffma2(acc[1][1], adB, xm1);
        }
    }
}

} // namespace

extern "C" __global__ void __launch_bounds__(128, 10)
hier_kernel(const int* __restrict__ tokens, const int* __restrict__ positions,
            const float* __restrict__ emb,
            const float* __restrict__ g1, const float* __restrict__ b1v,
            const float* __restrict__ g2, const float* __restrict__ b2v,
            float* __restrict__ out)
{
    __shared__ PosSmem sm[2];

    const int tid  = (int)threadIdx.x;
    const int ph   = tid >> 6;            // position within CTA (0/1)
    const int t    = tid & 63;            // thread within position
    const int lane = tid & 31;
    const int wp   = (tid >> 5) & 1;      // warp within position
    const int sidx = blockIdx.x * 2 + ph;
    const float sf  = (float)positions[sidx];
    const float sf2 = TWO_PI_F * sf;
    PosSmem& PS = sm[ph];

    // ---- gather char embeddings ------------------------------------------
    {
        #pragma unroll
        for (int b = 0; b < B; ++b) {
            int tk = tokens[b * S + sidx];
            PS.xs2[b >> 1][t][b & 1] = emb[tk * V + t];
        }
    }
    __syncthreads();

    // ---- layer 0: h = (char_P .* phi64) @ x ------------------------------
    // thread t owns row i=t for BOTH pairs (phase computed once per (i,j)).
    {
        const int i = t;
        const float pbase = (float)(i * V + 2);
        unsigned long long acc0 = 0, acc1 = 0;
        #pragma unroll 8
        for (int j2 = 0; j2 < V / 2; ++j2) {
            ulonglong2 x0 = *reinterpret_cast<const ulonglong2*>(&PS.xs2[0][2 * j2][0]);
            ulonglong2 x1 = *reinterpret_cast<const ulonglong2*>(&PS.xs2[1][2 * j2][0]);
            #pragma unroll
            for (int e = 0; e < 2; ++e) {
                int j = 2 * j2 + e;
                float2 wr = g_pk0[j * V + i];
                float a = wr.x * phase_slow(sf, pbase + (float)j, wr.y);
                unsigned long long ad = dup2(a);
                ffma2(acc0, ad, e ? x0.y : x0.x);
                ffma2(acc1, ad, e ? x1.y : x1.x);
            }
        }
        *reinterpret_cast<unsigned long long*>(&PS.hs2[0][i][0]) = acc0;
        *reinterpret_cast<unsigned long long*>(&PS.hs2[1][i][0]) = acc1;
    }
    __syncthreads();

    const int i0 = t, i1 = t + 64;        // the two rows this thread owns

    // layernorm over 128 rows distributed 2/thread across 64 threads.
    auto layernorm2 = [&](float (&tv)[2][B], const float* gg, const float* bb,
                          float (&nv)[2][B]) {
        float s1[B], s2[B];
        #pragma unroll
        for (int b = 0; b < B; ++b) {
            s1[b] = tv[0][b] + tv[1][b];
            s2[b] = tv[0][b] * tv[0][b] + tv[1][b] * tv[1][b];
        }
        #pragma unroll
        for (int o = 16; o; o >>= 1) {
            #pragma unroll
            for (int b = 0; b < B; ++b) {
                s1[b] += __shfl_xor_sync(0xffffffffu, s1[b], o);
                s2[b] += __shfl_xor_sync(0xffffffffu, s2[b], o);
            }
        }
        if (lane == 0) {
            #pragma unroll
            for (int b = 0; b < B; ++b) {
                PS.red[0][b][wp] = s1[b];
                PS.red[1][b][wp] = s2[b];
            }
        }
        __syncthreads();
        const float gA = gg[i0], bA = bb[i0];
        const float gB = gg[i1], bB = bb[i1];
        #pragma unroll
        for (int b = 0; b < B; ++b) {
            float su = PS.red[0][b][0] + PS.red[0][b][1];
            float sq = PS.red[1][b][0] + PS.red[1][b][1];
            float mu  = su * (1.0f / D);
            float var = fmaf(sq, 1.0f / D, -mu * mu);
            float rs  = rsqrtf(var + 1e-5f);
            nv[0][b] = fmaf((tv[0][b] - mu) * rs, gA, bA);
            nv[1][b] = fmaf((tv[1][b] - mu) * rs, gB, bB);
        }
    };

    // ---- layer 1: t1 = M1 @ h and rv = R1 @ h (fused, 2 rows) ------------
    unsigned long long t1p[2][2] = {{0ull,0ull},{0ull,0ull}};
    unsigned long long rvp[2][2] = {{0ull,0ull},{0ull,0ull}};
    {
        #pragma unroll 8
        for (int j2 = 0; j2 < V / 2; ++j2) {
            ulonglong2 x0 = *reinterpret_cast<const ulonglong2*>(&PS.hs2[0][2 * j2][0]);
            ulonglong2 x1 = *reinterpret_cast<const ulonglong2*>(&PS.hs2[1][2 * j2][0]);
            #pragma unroll
            for (int e = 0; e < 2; ++e) {
                int j = 2 * j2 + e;
                float2 wA = g_mr[j * D + i0];
                float2 wB = g_mr[j * D + i1];
                unsigned long long xm0 = e ? x0.y : x0.x;
                unsigned long long xm1 = e ? x1.y : x1.x;
                unsigned long long mA = dup2(wA.x), rA = dup2(wA.y);
                unsigned long long mB = dup2(wB.x), rB = dup2(wB.y);
                ffma2(t1p[0][0], mA, xm0); ffma2(t1p[0][1], mA, xm1);
                ffma2(t1p[1][0], mB, xm0); ffma2(t1p[1][1], mB, xm1);
                ffma2(rvp[0][0], rA, xm0); ffma2(rvp[0][1], rA, xm1);
                ffma2(rvp[1][0], rB, xm0); ffma2(rvp[1][1], rB, xm1);
            }
        }
    }
    // layernorm(t1) -> ls2
    {
        float tv[2][B], nv[2][B];
        #pragma unroll
        for (int r = 0; r < 2; ++r) {
            float2 a0 = unpk(t1p[r][0]), a1 = unpk(t1p[r][1]);
            tv[r][0] = a0.x; tv[r][1] = a0.y; tv[r][2] = a1.x; tv[r][3] = a1.y;
        }
        layernorm2(tv, g1, b1v, nv);
        *reinterpret_cast<unsigned long long*>(&PS.ls2[0][i0][0]) = pk2(nv[0][0], nv[0][1]);
        *reinterpret_cast<unsigned long long*>(&PS.ls2[1][i0][0]) = pk2(nv[0][2], nv[0][3]);
        *reinterpret_cast<unsigned long long*>(&PS.ls2[0][i1][0]) = pk2(nv[1][0], nv[1][1]);
        *reinterpret_cast<unsigned long long*>(&PS.ls2[1][i1][0]) = pk2(nv[1][2], nv[1][3]);
    }
    __syncthreads();

    const float pb0 = (float)(i0 * D + 2);

    // ---- layer 1 pos_nk + residual ---------------------------------------
    unsigned long long h1p[2][2] = {{0ull,0ull},{0ull,0ull}};
    {
        const float* xbase = &PS.ls2[0][0][0];
        if (i0 >= 32) posnk_accum<true >(g_pk1, xbase, sf, sf2, pb0, i0, i1, h1p);
        else          posnk_accum<false>(g_pk1, xbase, sf, sf2, pb0, i0, i1, h1p);
        #pragma unroll
        for (int r = 0; r < 2; ++r) {
            h1p[r][0] = addp(h1p[r][0], rvp[r][0]);
            h1p[r][1] = addp(h1p[r][1], rvp[r][1]);
        }
        *reinterpret_cast<unsigned long long*>(&PS.h1s2[0][i0][0]) = h1p[0][0];
        *reinterpret_cast<unsigned long long*>(&PS.h1s2[1][i0][0]) = h1p[0][1];
        *reinterpret_cast<unsigned long long*>(&PS.h1s2[0][i1][0]) = h1p[1][0];
        *reinterpret_cast<unsigned long long*>(&PS.h1s2[1][i1][0]) = h1p[1][1];
    }
    __syncthreads();

    // ---- layer 2: t2 = M2 @ h1 -------------------------------------------
    unsigned long long t2p[2][2] = {{0ull,0ull},{0ull,0ull}};
    {
        #pragma unroll 8
        for (int j2 = 0; j2 < D / 2; ++j2) {
            ulonglong2 x0 = *reinterpret_cast<const ulonglong2*>(&PS.h1s2[0][2 * j2][0]);
            ulonglong2 x1 = *reinterpret_cast<const ulonglong2*>(&PS.h1s2[1][2 * j2][0]);
            #pragma unroll
            for (int e = 0; e < 2; ++e) {
                int j = 2 * j2 + e;
                unsigned long long mA = dup2(g_M2T[j * D + i0]);
                unsigned long long mB = dup2(g_M2T[j * D + i1]);
                unsigned long long xm0 = e ? x0.y : x0.x;
                unsigned long long xm1 = e ? x1.y : x1.x;
                ffma2(t2p[0][0], mA, xm0); ffma2(t2p[0][1], mA, xm1);
                ffma2(t2p[1][0], mB, xm0); ffma2(t2p[1][1], mB, xm1);
            }
        }
    }
    // layernorm(t2) -> ls2 (safe: last ls2 readers finished before h1 sync)
    {
        float tv[2][B], nv[2][B];
        #pragma unroll
        for (int r = 0; r < 2; ++r) {
            float2 a0 = unpk(t2p[r][0]), a1 = unpk(t2p[r][1]);
            tv[r][0] = a0.x; tv[r][1] = a0.y; tv[r][2] = a1.x; tv[r][3] = a1.y;
        }
        layernorm2(tv, g2, b2v, nv);
        __syncthreads();
        *reinterpret_cast<unsigned long long*>(&PS.ls2[0][i0][0]) = pk2(nv[0][0], nv[0][1]);
        *reinterpret_cast<unsigned long long*>(&PS.ls2[1][i0][0]) = pk2(nv[0][2], nv[0][3]);
        *reinterpret_cast<unsigned long long*>(&PS.ls2[0][i1][0]) = pk2(nv[1][0], nv[1][1]);
        *reinterpret_cast<unsigned long long*>(&PS.ls2[1][i1][0]) = pk2(nv[1][2], nv[1][3]);
    }
    __syncthreads();

    // ---- layer 2 pos_nk + shared residual t2 ------------------------------
    unsigned long long ovp[2][2] = {{0ull,0ull},{0ull,0ull}};
    {
        const float* xbase = &PS.ls2[0][0][0];
        if (i0 >= 32) posnk_accum<true >(g_pk2, xbase, sf, sf2, pb0, i0, i1, ovp);
        else          posnk_accum<false>(g_pk2, xbase, sf, sf2, pb0, i0, i1, ovp);
    }
    {
        float2 o00 = unpk(addp(ovp[0][0], t2p[0][0]));   // row i0, batches 0/1
        float2 o01 = unpk(addp(ovp[0][1], t2p[0][1]));   // row i0, batches 2/3
        float2 o10 = unpk(addp(ovp[1][0], t2p[1][0]));   // row i1, batches 0/1
        float2 o11 = unpk(addp(ovp[1][1], t2p[1][1]));   // row i1, batches 2/3
        out[(0 * S + sidx) * D + i0] = o00.x;
        out[(1 * S + sidx) * D + i0] = o00.y;
        out[(2 * S + sidx) * D + i0] = o01.x;
        out[(3 * S + sidx) * D + i0] = o01.y;
        out[(0 * S + sidx) * D + i1] = o10.x;
        out[(1 * S + sidx) * D + i1] = o10.y;
        out[(2 * S + sidx) * D + i1] = o11.x;
        out[(3 * S + sidx) * D + i1] = o11.y;
    }
}

extern "C" void kernel_launch(void* const* d_in, const int* in_sizes, int n_in,
                              void* d_out, int out_size) {
    const int*   tokens    = (const int*)d_in[0];
    const int*   positions = (const int*)d_in[1];
    const float* emb       = (const float*)d_in[2];
    const float* charP     = (const float*)d_in[3];
    const float* M1        = (const float*)d_in[4];
    const float* P1        = (const float*)d_in[5];
    const float* g1        = (const float*)d_in[6];
    const float* b1        = (const float*)d_in[7];
    const float* R1        = (const float*)d_in[8];
    const float* M2        = (const float*)d_in[9];
    const float* P2        = (const float*)d_in[10];
    const float* g2        = (const float*)d_in[11];
    const float* b2        = (const float*)d_in[12];
    float* out = (float*)d_out;

    prep_weights<<<(61440 + 255) / 256, 256>>>(charP, M1, R1, P1, P2, M2);

    hier_kernel<<<S / 2, 128>>>(tokens, positions, emb, g1, b1, g2, b2, out);
}